// round 13
// baseline (speedup 1.0000x reference)
#include <cuda_runtime.h>
#include <cuda_fp16.h>

// Problem constants: B=2048, T=512, I=4, H=64, O=4
#define TT 512
#define BB 2048
#define HH 64
#define OO 4
#define NB 16    // batch rows per block = mma M tile (exact: 2048 = 128*16)
#define GRID 128
#define NT 512   // 16 warps; warp w owns gate-columns [16w, 16w+16)
#define HW 88    // A row width in halfs: 0-63 h, 64-67 x, 68 bias-one, 69-87 zero

__device__ __forceinline__ float tanh_ap(float x){
    float r; asm("tanh.approx.f32 %0, %1;" : "=f"(r) : "f"(x)); return r;
}
__device__ __forceinline__ float sig_ap(float x){
    return __fmaf_rn(0.5f, tanh_ap(0.5f * x), 0.5f);
}
__device__ __forceinline__ unsigned packh2(float lo, float hi){
    __half2 h = __floats2half2_rn(lo, hi);
    return *reinterpret_cast<unsigned*>(&h);
}
// D = A(16x16 f16, row) * B(16x8 f16, col) + D (f32)
__device__ __forceinline__ void mma16816(float* c, const unsigned* a, unsigned b0, unsigned b1){
    asm volatile(
        "mma.sync.aligned.m16n8k16.row.col.f32.f16.f16.f32 "
        "{%0,%1,%2,%3}, {%4,%5,%6,%7}, {%8,%9}, {%0,%1,%2,%3};\n"
        : "+f"(c[0]), "+f"(c[1]), "+f"(c[2]), "+f"(c[3])
        : "r"(a[0]), "r"(a[1]), "r"(a[2]), "r"(a[3]), "r"(b0), "r"(b1));
}
__device__ __forceinline__ void ldsm_x4(unsigned &r0, unsigned &r1, unsigned &r2, unsigned &r3,
                                        unsigned addr){
    asm volatile("ldmatrix.sync.aligned.m8n8.x4.shared.b16 {%0,%1,%2,%3}, [%4];"
                 : "=r"(r0), "=r"(r1), "=r"(r2), "=r"(r3) : "r"(addr));
}
__device__ __forceinline__ unsigned smem_u32(const void* p){
    return (unsigned)__cvta_generic_to_shared(p);
}

__global__ void __launch_bounds__(NT, 1) lstm_mma_kernel(
    const float* __restrict__ x,     // [B, T, I]
    const float* __restrict__ W_ih,  // [4H, I]
    const float* __restrict__ W_hh,  // [4H, H]
    const float* __restrict__ b_ih,  // [4H]
    const float* __restrict__ b_hh,  // [4H]
    const float* __restrict__ W_fc,  // [O, H]
    const float* __restrict__ b_fc,  // [O]
    float* __restrict__ out)         // [1, B, O]
{
    __shared__ __half h_sh[2][NB][HW];   // double-buffered augmented A matrix (fp16)

    const int tid  = threadIdx.x;
    const int wid  = tid >> 5;           // 0..15
    const int lane = tid & 31;
    const int g    = lane >> 2;
    const int ti   = lane & 3;
    const int bbase = blockIdx.x * NB;

    // Gate-column permutation: col = 4*u + {0:i,1:g,2:f,3:o}; W rows i:0-63 f:64-127 g:128-191 o:192-255
    // ---- B fragments (stationary weights): [nt 0..1][kt 0..4] ----
    unsigned bf0[2][5], bf1[2][5];
    #pragma unroll
    for (int nt = 0; nt < 2; nt++){
        int ncol = wid*16 + nt*8 + g;
        int u  = ncol >> 2;
        int gt = ncol & 3;
        int wrow = u + (gt == 0 ? 0 : gt == 1 ? 128 : gt == 2 ? 64 : 192);
        #pragma unroll
        for (int kt = 0; kt < 4; kt++){
            const float* wr = W_hh + (size_t)wrow * HH + kt*16;
            bf0[nt][kt] = packh2(wr[2*ti],     wr[2*ti + 1]);
            bf1[nt][kt] = packh2(wr[2*ti + 8], wr[2*ti + 9]);
        }
        // kt=4: k rows 64-67 = W_ih, 68 = bias, rest 0
        float e0 = 0.f, e1 = 0.f;
        if (ti < 2){ e0 = W_ih[wrow*4 + 2*ti]; e1 = W_ih[wrow*4 + 2*ti + 1]; }
        else if (ti == 2){ e0 = b_ih[wrow] + b_hh[wrow]; }
        bf0[nt][4] = packh2(e0, e1);
        bf1[nt][4] = 0u;
    }

    // ---- ldmatrix per-lane source offsets ----
    const int lrow = (lane & 7) + ((lane >> 3) & 1) * 8;
    const int lcol = (lane >> 4) << 3;
    const unsigned abase0 = smem_u32(&h_sh[0][lrow][lcol]);
    const unsigned abase1 = smem_u32(&h_sh[1][lrow][lcol]);

    // ---- init shared: zero both buffers, bias-one col, x(t=0) ----
    for (int i = tid; i < 2*NB*HW; i += NT) ((__half*)h_sh)[i] = __float2half(0.f);
    __syncthreads();
    if (tid < 2*NB){
        int p = tid >> 4, r = tid & 15;
        h_sh[p][r][68] = __float2half(1.f);
    }
    if (tid < NB){
        float4 xv = ((const float4*)x)[ (size_t)(bbase + tid) * TT ];
        h_sh[0][tid][64] = __float2half(xv.x);
        h_sh[0][tid][65] = __float2half(xv.y);
        h_sh[0][tid][66] = __float2half(xv.z);
        h_sh[0][tid][67] = __float2half(xv.w);
    }
    __syncthreads();

    // cell state (odd-ti lanes meaningful): [nt][slot]
    float cst[2][2];
    cst[0][0] = 0.f; cst[0][1] = 0.f; cst[1][0] = 0.f; cst[1][1] = 0.f;

    const float cm = (ti & 1) ? 0.5f : 1.0f;   // act1: tanh (even ti: g) / sigmoid (odd ti: o)
    const float ca = (ti & 1) ? 0.5f : 0.0f;

    for (int t = 0; t < TT; t++){
        const int p = t & 1;
        const unsigned abase = p ? abase1 : abase0;

        // prefetch next x
        float4 xn;
        const bool pre = (tid < NB) && (t + 1 < TT);
        if (pre) xn = ((const float4*)x)[ (size_t)(bbase + tid) * TT + (t + 1) ];

        // ---- A fragments via ldmatrix.x4 ----
        unsigned af[5][4];
        #pragma unroll
        for (int kt = 0; kt < 5; kt++)
            ldsm_x4(af[kt][0], af[kt][1], af[kt][2], af[kt][3], abase + kt*32);

        // ---- gates = [h | x | 1] @ Waug^T (fp32 accum, 2 independent chains) ----
        float C[2][4];
        C[0][0] = 0.f; C[0][1] = 0.f; C[0][2] = 0.f; C[0][3] = 0.f;
        C[1][0] = 0.f; C[1][1] = 0.f; C[1][2] = 0.f; C[1][3] = 0.f;
        #pragma unroll
        for (int kt = 0; kt < 5; kt++){
            mma16816(C[0], af[kt], bf0[0][kt], bf1[0][kt]);
            mma16816(C[1], af[kt], bf0[1][kt], bf1[1][kt]);
        }

        // ---- epilogue: activations + lane-pair cell update + h writeback ----
        #pragma unroll
        for (int nt = 0; nt < 2; nt++){
            const int u = wid*4 + nt*2 + (ti >> 1);
            #pragma unroll
            for (int s = 0; s < 2; s++){
                float v0 = C[nt][2*s];          // i (even ti) / f (odd ti)
                float v1 = C[nt][2*s + 1];      // g (even ti) / o (odd ti)
                float a0 = sig_ap(v0);
                float a1 = __fmaf_rn(cm, tanh_ap(cm * v1), ca);
                float pp = a0 * a1;                               // sig(i)*tanh(g) on even
                float q  = __shfl_xor_sync(0xffffffffu, pp, 1);
                float cs = __fmaf_rn(a0, cst[nt][s], q);          // sig(f)*c + sig(i)tanh(g)
                cst[nt][s] = cs;
                float hv = a1 * tanh_ap(cs);                      // sig(o)*tanh(c)
                if (ti & 1){
                    int row = s ? (g + 8) : g;
                    h_sh[p ^ 1][row][u] = __float2half(hv);
                }
            }
        }

        // stage next x into the buffer being written this step
        if (pre){
            h_sh[p ^ 1][tid][64] = __float2half(xn.x);
            h_sh[p ^ 1][tid][65] = __float2half(xn.y);
            h_sh[p ^ 1][tid][66] = __float2half(xn.z);
            h_sh[p ^ 1][tid][67] = __float2half(xn.w);
        }
        __syncthreads();
    }

    // ---- FC head: final h in buffer 0 (TT even) ----
    if (tid < NB * OO){
        const int b = tid >> 2, o = tid & 3;
        float s = b_fc[o];
        #pragma unroll
        for (int k = 0; k < HH; k++)
            s = __fmaf_rn(W_fc[o*HH + k], __half2float(h_sh[0][b][k]), s);
        out[(size_t)(bbase + b) * OO + o] = s;
    }
}

extern "C" void kernel_launch(void* const* d_in, const int* in_sizes, int n_in,
                              void* d_out, int out_size)
{
    const float* x    = (const float*)d_in[0];
    const float* W_ih = (const float*)d_in[1];
    const float* W_hh = (const float*)d_in[2];
    const float* b_ih = (const float*)d_in[3];
    const float* b_hh = (const float*)d_in[4];
    const float* W_fc = (const float*)d_in[5];
    const float* b_fc = (const float*)d_in[6];
    float* out = (float*)d_out;

    lstm_mma_kernel<<<GRID, NT>>>(x, W_ih, W_hh, b_ih, b_hh, W_fc, b_fc, out);
}

// round 14
// speedup vs baseline: 1.2500x; 1.2500x over previous
#include <cuda_runtime.h>
#include <cuda_fp16.h>

// Problem constants: B=2048, T=512, I=4, H=64, O=4
#define TT 512
#define BB 2048
#define HH 64
#define OO 4
#define NB 16    // batch rows per block = mma M tile (exact: 2048 = 128*16)
#define GRID 128
#define NT 256   // 8 warps; warp w owns hidden units [8w, 8w+8)
#define HW 88    // A row width in halfs: 0-63 h, 64-67 x, 68 bias-one, 69-87 zero

__device__ __forceinline__ float tanh_ap(float x){
    float r; asm("tanh.approx.f32 %0, %1;" : "=f"(r) : "f"(x)); return r;
}
__device__ __forceinline__ float sig_ap(float x){
    return __fmaf_rn(0.5f, tanh_ap(0.5f * x), 0.5f);
}
__device__ __forceinline__ unsigned packh2(float lo, float hi){
    __half2 h = __floats2half2_rn(lo, hi);
    return *reinterpret_cast<unsigned*>(&h);
}
// D = A(16x16 f16, row) * B(16x8 f16, col) + D (f32)
__device__ __forceinline__ void mma16816(float* c, const unsigned* a, unsigned b0, unsigned b1){
    asm volatile(
        "mma.sync.aligned.m16n8k16.row.col.f32.f16.f16.f32 "
        "{%0,%1,%2,%3}, {%4,%5,%6,%7}, {%8,%9}, {%0,%1,%2,%3};\n"
        : "+f"(c[0]), "+f"(c[1]), "+f"(c[2]), "+f"(c[3])
        : "r"(a[0]), "r"(a[1]), "r"(a[2]), "r"(a[3]), "r"(b0), "r"(b1));
}
__device__ __forceinline__ void ldsm_x4(unsigned &r0, unsigned &r1, unsigned &r2, unsigned &r3,
                                        unsigned addr){
    asm volatile("ldmatrix.sync.aligned.m8n8.x4.shared.b16 {%0,%1,%2,%3}, [%4];"
                 : "=r"(r0), "=r"(r1), "=r"(r2), "=r"(r3) : "r"(addr));
}
__device__ __forceinline__ unsigned smem_u32(const void* p){
    return (unsigned)__cvta_generic_to_shared(p);
}

__global__ void __launch_bounds__(NT, 1) lstm_mma_kernel(
    const float* __restrict__ x,     // [B, T, I]
    const float* __restrict__ W_ih,  // [4H, I]
    const float* __restrict__ W_hh,  // [4H, H]
    const float* __restrict__ b_ih,  // [4H]
    const float* __restrict__ b_hh,  // [4H]
    const float* __restrict__ W_fc,  // [O, H]
    const float* __restrict__ b_fc,  // [O]
    float* __restrict__ out)         // [1, B, O]
{
    __shared__ __half h_sh[2][NB][HW];   // double-buffered augmented A matrix (fp16)

    const int tid  = threadIdx.x;
    const int wid  = tid >> 5;           // 0..7
    const int lane = tid & 31;
    const int g    = lane >> 2;
    const int ti   = lane & 3;
    const int bbase = blockIdx.x * NB;

    // New gate-column permutation (per warp, 4 n-tiles = 32 cols):
    //   tile pair p = nt>>1 covers units u = wid*8 + p*4 + (n>>1)
    //   even tile (nt&1==0): col n = 2k   -> gate i of unit,  2k+1 -> gate g
    //   odd  tile (nt&1==1): col n = 2k   -> gate f,          2k+1 -> gate o
    // W row offsets: i:0, f:64, g:128, o:192.

    // ---- B fragments (stationary weights): [nt 0..3][kt 0..4] ----
    unsigned bf0[4][5], bf1[4][5];
    #pragma unroll
    for (int nt = 0; nt < 4; nt++){
        int n  = g;                                  // fragment n index = lane>>2
        int u  = wid*8 + (nt >> 1)*4 + (n >> 1);
        int gate = (nt & 1) ? ((n & 1) ? 3 : 1)      // odd tile: f / o
                            : ((n & 1) ? 2 : 0);     // even tile: i / g
        int wrow = u + (gate == 0 ? 0 : gate == 1 ? 64 : gate == 2 ? 128 : 192);
        #pragma unroll
        for (int kt = 0; kt < 4; kt++){
            const float* wr = W_hh + (size_t)wrow * HH + kt*16;
            bf0[nt][kt] = packh2(wr[2*ti],     wr[2*ti + 1]);
            bf1[nt][kt] = packh2(wr[2*ti + 8], wr[2*ti + 9]);
        }
        // kt=4: k rows 64-67 = W_ih, 68 = bias, rest 0
        float e0 = 0.f, e1 = 0.f;
        if (ti < 2){ e0 = W_ih[wrow*4 + 2*ti]; e1 = W_ih[wrow*4 + 2*ti + 1]; }
        else if (ti == 2){ e0 = b_ih[wrow] + b_hh[wrow]; }
        bf0[nt][4] = packh2(e0, e1);
        bf1[nt][4] = 0u;
    }

    // ---- ldmatrix per-lane source offsets ----
    const int lrow = (lane & 7) + ((lane >> 3) & 1) * 8;
    const int lcol = (lane >> 4) << 3;
    const unsigned abase0 = smem_u32(&h_sh[0][lrow][lcol]);
    const unsigned abase1 = smem_u32(&h_sh[1][lrow][lcol]);

    // ---- init shared: zero both buffers, bias-one col, x(t=0) ----
    for (int i = tid; i < 2*NB*HW; i += NT) ((__half*)h_sh)[i] = __float2half(0.f);
    __syncthreads();
    if (tid < 2*NB){
        int p = tid >> 4, r = tid & 15;
        h_sh[p][r][68] = __float2half(1.f);
    }
    if (tid < NB){
        float4 xv = ((const float4*)x)[ (size_t)(bbase + tid) * TT ];
        h_sh[0][tid][64] = __float2half(xv.x);
        h_sh[0][tid][65] = __float2half(xv.y);
        h_sh[0][tid][66] = __float2half(xv.z);
        h_sh[0][tid][67] = __float2half(xv.w);
    }
    __syncthreads();

    // cell state: cc[p][s] = c for unit (wid*8 + p*4 + ti), batch row (s ? g+8 : g)
    float cc[2][2];
    cc[0][0] = 0.f; cc[0][1] = 0.f; cc[1][0] = 0.f; cc[1][1] = 0.f;

    for (int t = 0; t < TT; t++){
        const int p = t & 1;
        const unsigned abase = p ? abase1 : abase0;

        // prefetch next x
        float4 xn;
        const bool pre = (tid < NB) && (t + 1 < TT);
        if (pre) xn = ((const float4*)x)[ (size_t)(bbase + tid) * TT + (t + 1) ];

        // ---- A fragments via ldmatrix.x4 ----
        unsigned af[5][4];
        #pragma unroll
        for (int kt = 0; kt < 5; kt++)
            ldsm_x4(af[kt][0], af[kt][1], af[kt][2], af[kt][3], abase + kt*32);

        // ---- gates = [h | x | 1] @ Waug^T (fp32 accum, 4 independent chains) ----
        float C[4][4];
        #pragma unroll
        for (int nt = 0; nt < 4; nt++){
            C[nt][0] = 0.f; C[nt][1] = 0.f; C[nt][2] = 0.f; C[nt][3] = 0.f;
        }
        #pragma unroll
        for (int kt = 0; kt < 5; kt++){
            #pragma unroll
            for (int nt = 0; nt < 4; nt++)
                mma16816(C[nt], af[kt], bf0[nt][kt], bf1[nt][kt]);
        }

        // ---- epilogue: all 4 gates of a unit live on THIS lane (no shfl) ----
        #pragma unroll
        for (int pp = 0; pp < 2; pp++){
            const int u = wid*8 + pp*4 + ti;
            #pragma unroll
            for (int s = 0; s < 2; s++){
                float vi = C[2*pp    ][2*s];
                float vg = C[2*pp    ][2*s + 1];
                float vf = C[2*pp + 1][2*s];
                float vo = C[2*pp + 1][2*s + 1];
                float ai = sig_ap(vi);
                float ag = tanh_ap(vg);
                float afv = sig_ap(vf);
                float ao = sig_ap(vo);
                float cs = __fmaf_rn(afv, cc[pp][s], ai * ag);
                cc[pp][s] = cs;
                float hv = ao * tanh_ap(cs);
                int row = s ? (g + 8) : g;
                h_sh[p ^ 1][row][u] = __float2half(hv);
            }
        }

        // stage next x into the buffer being written this step
        if (pre){
            h_sh[p ^ 1][tid][64] = __float2half(xn.x);
            h_sh[p ^ 1][tid][65] = __float2half(xn.y);
            h_sh[p ^ 1][tid][66] = __float2half(xn.z);
            h_sh[p ^ 1][tid][67] = __float2half(xn.w);
        }
        __syncthreads();
    }

    // ---- FC head: final h in buffer 0 (TT even) ----
    if (tid < NB * OO){
        const int b = tid >> 2, o = tid & 3;
        float s = b_fc[o];
        #pragma unroll
        for (int k = 0; k < HH; k++)
            s = __fmaf_rn(W_fc[o*HH + k], __half2float(h_sh[0][b][k]), s);
        out[(size_t)(bbase + b) * OO + o] = s;
    }
}

extern "C" void kernel_launch(void* const* d_in, const int* in_sizes, int n_in,
                              void* d_out, int out_size)
{
    const float* x    = (const float*)d_in[0];
    const float* W_ih = (const float*)d_in[1];
    const float* W_hh = (const float*)d_in[2];
    const float* b_ih = (const float*)d_in[3];
    const float* b_hh = (const float*)d_in[4];
    const float* W_fc = (const float*)d_in[5];
    const float* b_fc = (const float*)d_in[6];
    float* out = (float*)d_out;

    lstm_mma_kernel<<<GRID, NT>>>(x, W_ih, W_hh, b_ih, b_hh, W_fc, b_fc, out);
}